// round 4
// baseline (speedup 1.0000x reference)
#include <cuda_runtime.h>
#include <cstdint>

#define BB 256
#define TT 512
#define II 64
#define HH 512
#define OO 24

#define CLUSTER_NCTAS 8
#define NCLUSTERS 16
#define NBLOCKS (CLUSTER_NCTAS * NCLUSTERS)   // 128
#define NTHREADS 256

#define BM 16        // batch rows per cluster
#define HC 64        // hidden cols per CTA (rank)
#define K2 (HH/2)    // 256 k-pairs
#define I2 (II/2)    // 32 i-pairs

// SMEM (float2 units)
#define WK2_F2 (K2 * HC)        // 16384 f2 = 128 KB
#define WI2_F2 (I2 * HC)        //  2048 f2 =  16 KB
#define HP2_F2 (K2 * BM)        //  4096 f2 =  32 KB
#define XS2_F2 (I2 * BM)        //   512 f2 =   4 KB
#define SMEM_F2 (WK2_F2 + WI2_F2 + HP2_F2 + XS2_F2)
#define SMEM_BYTES (SMEM_F2 * 8 + HC * 4)     // + bias = 184576 B

// Hidden state, k-major across full batch: g_h[parity][k][b]
__device__ float g_h[2][HH * BB];

__device__ __forceinline__ float2 ffma2(float2 a, float2 b, float2 c) {
    unsigned long long A, B, C, D;
    asm("mov.b64 %0, {%1, %2};" : "=l"(A) : "f"(a.x), "f"(a.y));
    asm("mov.b64 %0, {%1, %2};" : "=l"(B) : "f"(b.x), "f"(b.y));
    asm("mov.b64 %0, {%1, %2};" : "=l"(C) : "f"(c.x), "f"(c.y));
    asm("fma.rn.f32x2 %0, %1, %2, %3;" : "=l"(D) : "l"(A), "l"(B), "l"(C));
    float2 d;
    asm("mov.b64 {%0, %1}, %2;" : "=f"(d.x), "=f"(d.y) : "l"(D));
    return d;
}
__device__ __forceinline__ float2 ld_cg_f2(const float* p) {
    float2 v;
    asm volatile("ld.global.cg.v2.f32 {%0,%1}, [%2];"
                 : "=f"(v.x), "=f"(v.y) : "l"(p) : "memory");
    return v;
}
__device__ __forceinline__ float ld_cg_f1(const float* p) {
    float v;
    asm volatile("ld.global.cg.f32 %0, [%1];" : "=f"(v) : "l"(p) : "memory");
    return v;
}

__global__ void __launch_bounds__(NTHREADS, 1) __cluster_dims__(CLUSTER_NCTAS, 1, 1)
rnn_persistent_kernel(const float* __restrict__ x,
                      const float* __restrict__ W_ih,
                      const float* __restrict__ W_hh,
                      const float* __restrict__ b_ih,
                      const float* __restrict__ b_hh)
{
    extern __shared__ float2 sm2[];
    float2* Wk2 = sm2;                       // [k2][HC] pairs (w[h][2k2], w[h][2k2+1])
    float2* Wi2 = Wk2 + WK2_F2;              // [i2][HC]
    float2* Hp2 = Wi2 + WI2_F2;              // [k2][BM] pairs (h[2k2][b], h[2k2+1][b])
    float2* Xs2 = Hp2 + HP2_F2;              // [i2][BM]
    float*  bsm = (float*)(Xs2 + XS2_F2);    // [HC]

    const int tid  = threadIdx.x;
    const int rank = blockIdx.x & (CLUSTER_NCTAS - 1);
    const int cl   = blockIdx.x >> 3;
    const int b0   = cl * BM;
    const int h0   = rank * HC;

    // ---- one-time weight staging ----
    // W_hh slice: 64 rows x 512 cols -> Wk2[k2][h]
    for (int n = 0; n < (HC * (HH / 4)) / NTHREADS; ++n) {      // 32 iters
        int idx = tid + n * NTHREADS;
        int k4 = idx >> 6;           // 0..127
        int h  = idx & (HC - 1);     // 0..63
        float4 w = *(const float4*)&W_hh[(size_t)(h0 + h) * HH + 4 * k4];
        Wk2[(2 * k4)     * HC + h] = make_float2(w.x, w.y);
        Wk2[(2 * k4 + 1) * HC + h] = make_float2(w.z, w.w);
    }
    // W_ih slice: 64 x 64 -> Wi2[i2][h]
    for (int n = 0; n < (HC * (II / 4)) / NTHREADS; ++n) {      // 4 iters
        int idx = tid + n * NTHREADS;
        int i4 = idx >> 6;           // 0..15
        int h  = idx & (HC - 1);
        float4 w = *(const float4*)&W_ih[(size_t)(h0 + h) * II + 4 * i4];
        Wi2[(2 * i4)     * HC + h] = make_float2(w.x, w.y);
        Wi2[(2 * i4 + 1) * HC + h] = make_float2(w.z, w.w);
    }
    if (tid < HC) bsm[tid] = b_ih[h0 + tid] + b_hh[h0 + tid];
    __syncthreads();

    const int b_l = tid & (BM - 1);      // 0..15
    const int h_l = (tid >> 4) << 2;     // 0,4,...,60
    const float bias0 = bsm[h_l + 0];
    const float bias1 = bsm[h_l + 1];
    const float bias2 = bsm[h_l + 2];
    const float bias3 = bsm[h_l + 3];

    const float2* ax = Xs2 + b_l;
    const float2* ah = Hp2 + b_l;
    const float2* wx = Wi2 + h_l;
    const float2* wh = Wk2 + h_l;

    for (int t = 0; t < TT; ++t) {
        const float* gprev = g_h[1 - (t & 1)];
        float*       gnew  = g_h[t & 1];

        // ---- stage x_t tile: Xs2[i2][b] ----
        #pragma unroll
        for (int n = 0; n < XS2_F2 / NTHREADS; ++n) {           // 2 iters
            int idx = tid + n * NTHREADS;
            int i2 = idx >> 4;
            int b  = idx & (BM - 1);
            const float* src = &x[((size_t)(b0 + b) * TT + t) * II + 2 * i2];
            Xs2[idx] = *(const float2*)src;
        }
        // ---- stage h_{t-1} tile from L2 (k-major): Hp2[k2][b] ----
        if (t > 0) {
            #pragma unroll
            for (int n = 0; n < HP2_F2 / NTHREADS; ++n) {       // 16 iters
                int idx = tid + n * NTHREADS;
                int k2 = idx >> 4;
                int b  = idx & (BM - 1);
                float lo = ld_cg_f1(&gprev[(2 * k2)     * BB + b0 + b]);
                float hi = ld_cg_f1(&gprev[(2 * k2 + 1) * BB + b0 + b]);
                Hp2[idx] = make_float2(lo, hi);
            }
        }
        __syncthreads();

        float2 acc0 = make_float2(0.f, 0.f), acc1 = make_float2(0.f, 0.f);
        float2 acc2 = make_float2(0.f, 0.f), acc3 = make_float2(0.f, 0.f);

        // ---- input projection over i2 pairs ----
        #pragma unroll
        for (int i2 = 0; i2 < I2; ++i2) {
            float2 a  = ax[i2 * BM];
            float4 wA = *(const float4*)&wx[i2 * HC];
            float4 wB = *(const float4*)&wx[i2 * HC + 2];
            acc0 = ffma2(a, make_float2(wA.x, wA.y), acc0);
            acc1 = ffma2(a, make_float2(wA.z, wA.w), acc1);
            acc2 = ffma2(a, make_float2(wB.x, wB.y), acc2);
            acc3 = ffma2(a, make_float2(wB.z, wB.w), acc3);
        }
        // ---- recurrent projection over k2 pairs ----
        if (t > 0) {
            #pragma unroll 8
            for (int k2 = 0; k2 < K2; ++k2) {
                float2 a  = ah[k2 * BM];
                float4 wA = *(const float4*)&wh[k2 * HC];
                float4 wB = *(const float4*)&wh[k2 * HC + 2];
                acc0 = ffma2(a, make_float2(wA.x, wA.y), acc0);
                acc1 = ffma2(a, make_float2(wA.z, wA.w), acc1);
                acc2 = ffma2(a, make_float2(wB.x, wB.y), acc2);
                acc3 = ffma2(a, make_float2(wB.z, wB.w), acc3);
            }
        }

        // ---- relu + publish to g_h[t&1] (k-major) ----
        float v0 = fmaxf(acc0.x + acc0.y + bias0, 0.f);
        float v1 = fmaxf(acc1.x + acc1.y + bias1, 0.f);
        float v2 = fmaxf(acc2.x + acc2.y + bias2, 0.f);
        float v3 = fmaxf(acc3.x + acc3.y + bias3, 0.f);
        const int bg = b0 + b_l;
        gnew[(h0 + h_l + 0) * BB + bg] = v0;
        gnew[(h0 + h_l + 1) * BB + bg] = v1;
        gnew[(h0 + h_l + 2) * BB + bg] = v2;
        gnew[(h0 + h_l + 3) * BB + bg] = v3;

        // ---- cluster barrier: release stores, acquire + L1D flush for peers ----
        __threadfence();
        asm volatile("barrier.cluster.arrive.aligned;" ::: "memory");
        asm volatile("barrier.cluster.wait.aligned;"   ::: "memory");
    }
}

// Epilogue: out[b][o] = sum_k h_T[k][b] * fc_w[o][k] + fc_b[o]
__global__ void __launch_bounds__(NTHREADS)
fc_kernel(const float* __restrict__ fc_w,
          const float* __restrict__ fc_b,
          float* __restrict__ out)
{
    int p = blockIdx.x * NTHREADS + threadIdx.x;   // 0..6143
    int b = p & (BB - 1);
    int o = p >> 8;
    const float* h = g_h[(TT - 1) & 1];            // parity 1
    const float* w = fc_w + (size_t)o * HH;
    float s = fc_b[o];
    #pragma unroll 8
    for (int k = 0; k < HH; ++k)
        s = fmaf(ld_cg_f1(&h[k * BB + b]), __ldg(&w[k]), s);
    out[b * OO + o] = s;
}

extern "C" void kernel_launch(void* const* d_in, const int* in_sizes, int n_in,
                              void* d_out, int out_size)
{
    const float* x    = (const float*)d_in[0];
    const float* W_ih = (const float*)d_in[1];
    const float* W_hh = (const float*)d_in[2];
    const float* b_ih = (const float*)d_in[3];
    const float* b_hh = (const float*)d_in[4];
    const float* fc_w = (const float*)d_in[5];
    const float* fc_b = (const float*)d_in[6];
    int nb = 0;
    for (int i = 0; i < n_in; ++i) {
        const float* p = (const float*)d_in[i];
        switch (in_sizes[i]) {
            case BB * TT * II: x    = p; break;
            case HH * II:      W_ih = p; break;
            case HH * HH:      W_hh = p; break;
            case OO * HH:      fc_w = p; break;
            case OO:           fc_b = p; break;
            case HH:           if (nb++ == 0) b_ih = p; else b_hh = p; break;
            default: break;
        }
    }
    float* out = (float*)d_out;

    cudaFuncSetAttribute(rnn_persistent_kernel,
                         cudaFuncAttributeMaxDynamicSharedMemorySize, SMEM_BYTES);
    rnn_persistent_kernel<<<NBLOCKS, NTHREADS, SMEM_BYTES>>>(x, W_ih, W_hh, b_ih, b_hh);
    fc_kernel<<<(BB * OO) / NTHREADS, NTHREADS>>>(fc_w, fc_b, out);
}

// round 5
// speedup vs baseline: 1.0022x; 1.0022x over previous
#include <cuda_runtime.h>
#include <cstdint>

#define BB 256
#define TT 512
#define II 64
#define HH 512
#define OO 24

#define CLUSTER_NCTAS 8
#define NCLUSTERS 16
#define NBLOCKS (CLUSTER_NCTAS * NCLUSTERS)   // 128
#define NTHREADS 256

#define BM 16        // batch rows per cluster
#define HC 64        // hidden cols per CTA (rank)
#define K2 (HH/2)    // 256 k-pairs
#define I2 (II/2)    // 32 i-pairs

// SMEM layout in float2 units
#define WK2_F2 (K2 * HC)        // 16384 f2 = 128 KB  W_hh slice
#define WI2_F2 (I2 * HC)        //  2048 f2 =  16 KB  W_ih slice
#define HP2_F2 (K2 * BM)        //  4096 f2 =  32 KB  h_{t-1} tile
#define XS2_F2 (I2 * BM)        //   512 f2 =   4 KB  x_t tile
#define SMEM_F2 (WK2_F2 + WI2_F2 + HP2_F2 + XS2_F2)
#define SMEM_BYTES (SMEM_F2 * 8 + HC * 4)     // 184576 B

typedef unsigned long long u64;

// Hidden state, k-major across batch: g_h[parity][k][b]
__device__ float g_h[2][HH * BB];

__device__ __forceinline__ float ld_cg_f1(const float* p) {
    float v;
    asm volatile("ld.global.cg.f32 %0, [%1];" : "=f"(v) : "l"(p) : "memory");
    return v;
}

// Packed dual-FMA on already-paired 64-bit registers: exactly one SASS FFMA2.
#define FFMA2(acc, a, w) \
    asm("fma.rn.f32x2 %0, %1, %2, %0;" : "+l"(acc) : "l"(a), "l"(w))

__global__ void __launch_bounds__(NTHREADS, 1) __cluster_dims__(CLUSTER_NCTAS, 1, 1)
rnn_persistent_kernel(const float* __restrict__ x,
                      const float* __restrict__ W_ih,
                      const float* __restrict__ W_hh,
                      const float* __restrict__ b_ih,
                      const float* __restrict__ b_hh)
{
    extern __shared__ float2 sm2[];
    float2* Wk2 = sm2;                       // [k2][HC]
    float2* Wi2 = Wk2 + WK2_F2;              // [i2][HC]
    float2* Hp2 = Wi2 + WI2_F2;              // [k2][BM]
    float2* Xs2 = Hp2 + HP2_F2;              // [i2][BM]
    float*  bsm = (float*)(Xs2 + XS2_F2);    // [HC]

    const int tid  = threadIdx.x;
    const int rank = blockIdx.x & (CLUSTER_NCTAS - 1);
    const int cl   = blockIdx.x >> 3;
    const int b0   = cl * BM;
    const int h0   = rank * HC;

    // ---- one-time weight staging ----
    for (int n = 0; n < (HC * (HH / 4)) / NTHREADS; ++n) {      // 32 iters
        int idx = tid + n * NTHREADS;
        int k4 = idx >> 6;
        int h  = idx & (HC - 1);
        float4 w = *(const float4*)&W_hh[(size_t)(h0 + h) * HH + 4 * k4];
        Wk2[(2 * k4)     * HC + h] = make_float2(w.x, w.y);
        Wk2[(2 * k4 + 1) * HC + h] = make_float2(w.z, w.w);
    }
    for (int n = 0; n < (HC * (II / 4)) / NTHREADS; ++n) {      // 4 iters
        int idx = tid + n * NTHREADS;
        int i4 = idx >> 6;
        int h  = idx & (HC - 1);
        float4 w = *(const float4*)&W_ih[(size_t)(h0 + h) * II + 4 * i4];
        Wi2[(2 * i4)     * HC + h] = make_float2(w.x, w.y);
        Wi2[(2 * i4 + 1) * HC + h] = make_float2(w.z, w.w);
    }
    if (tid < HC) bsm[tid] = b_ih[h0 + tid] + b_hh[h0 + tid];
    __syncthreads();

    const int b_l = tid & (BM - 1);      // 0..15
    const int h_l = (tid >> 4) << 2;     // 0,4,...,60
    const float bias0 = bsm[h_l + 0];
    const float bias1 = bsm[h_l + 1];
    const float bias2 = bsm[h_l + 2];
    const float bias3 = bsm[h_l + 3];

    // 64-bit views for packed loads (all 8B/16B aligned by construction)
    const u64*        axq = (const u64*)(Xs2 + b_l);
    const u64*        ahq = (const u64*)(Hp2 + b_l);
    const ulonglong2* wxq = (const ulonglong2*)(Wi2 + h_l);   // 16B: h_l..h_l+3, one k-pair
    const ulonglong2* whq = (const ulonglong2*)(Wk2 + h_l);

    for (int t = 0; t < TT; ++t) {
        const float* gprev = g_h[1 - (t & 1)];
        float*       gnew  = g_h[t & 1];

        // ---- stage x_t tile: Xs2[i2][b] ----
        #pragma unroll
        for (int n = 0; n < XS2_F2 / NTHREADS; ++n) {
            int idx = tid + n * NTHREADS;
            int i2 = idx >> 4;
            int b  = idx & (BM - 1);
            Xs2[idx] = *(const float2*)&x[((size_t)(b0 + b) * TT + t) * II + 2 * i2];
        }
        // ---- stage h_{t-1} tile from L2: Hp2[k2][b] ----
        if (t > 0) {
            #pragma unroll
            for (int n = 0; n < HP2_F2 / NTHREADS; ++n) {
                int idx = tid + n * NTHREADS;
                int k2 = idx >> 4;
                int b  = idx & (BM - 1);
                float lo = ld_cg_f1(&gprev[(2 * k2)     * BB + b0 + b]);
                float hi = ld_cg_f1(&gprev[(2 * k2 + 1) * BB + b0 + b]);
                Hp2[idx] = make_float2(lo, hi);
            }
        }
        __syncthreads();

        u64 acc0 = 0ull, acc1 = 0ull, acc2 = 0ull, acc3 = 0ull;  // packed {0.f,0.f}

        // ---- input projection (i2 pairs) ----
        #pragma unroll
        for (int i2 = 0; i2 < I2; ++i2) {
            u64 a = axq[i2 * (BM / 1)];                 // Xs2 stride BM f2 = BM u64
            ulonglong2 wA = wxq[i2 * (HC / 2)];         // 16B
            ulonglong2 wB = wxq[i2 * (HC / 2) + 1];     // next 16B
            FFMA2(acc0, a, wA.x);
            FFMA2(acc1, a, wA.y);
            FFMA2(acc2, a, wB.x);
            FFMA2(acc3, a, wB.y);
        }
        // ---- recurrent projection (k2 pairs) ----
        if (t > 0) {
            #pragma unroll 16
            for (int k2 = 0; k2 < K2; ++k2) {
                u64 a = ahq[k2 * BM];
                ulonglong2 wA = whq[k2 * (HC / 2)];
                ulonglong2 wB = whq[k2 * (HC / 2) + 1];
                FFMA2(acc0, a, wA.x);
                FFMA2(acc1, a, wA.y);
                FFMA2(acc2, a, wB.x);
                FFMA2(acc3, a, wB.y);
            }
        }

        // ---- unpack once, relu + publish (k-major) ----
        float a0x, a0y, a1x, a1y, a2x, a2y, a3x, a3y;
        asm("mov.b64 {%0,%1}, %2;" : "=f"(a0x), "=f"(a0y) : "l"(acc0));
        asm("mov.b64 {%0,%1}, %2;" : "=f"(a1x), "=f"(a1y) : "l"(acc1));
        asm("mov.b64 {%0,%1}, %2;" : "=f"(a2x), "=f"(a2y) : "l"(acc2));
        asm("mov.b64 {%0,%1}, %2;" : "=f"(a3x), "=f"(a3y) : "l"(acc3));
        float v0 = fmaxf(a0x + a0y + bias0, 0.f);
        float v1 = fmaxf(a1x + a1y + bias1, 0.f);
        float v2 = fmaxf(a2x + a2y + bias2, 0.f);
        float v3 = fmaxf(a3x + a3y + bias3, 0.f);
        const int bg = b0 + b_l;
        gnew[(h0 + h_l + 0) * BB + bg] = v0;
        gnew[(h0 + h_l + 1) * BB + bg] = v1;
        gnew[(h0 + h_l + 2) * BB + bg] = v2;
        gnew[(h0 + h_l + 3) * BB + bg] = v3;

        // ---- cluster barrier (release h stores to peers; acquire theirs) ----
        asm volatile("fence.acq_rel.cluster;" ::: "memory");
        asm volatile("barrier.cluster.arrive.aligned;" ::: "memory");
        asm volatile("barrier.cluster.wait.aligned;"   ::: "memory");
    }
}

// Epilogue: one warp per (o,b) output, shfl reduction over k.
__global__ void __launch_bounds__(256)
fc_kernel(const float* __restrict__ fc_w,
          const float* __restrict__ fc_b,
          float* __restrict__ out)
{
    int warp = (blockIdx.x * 256 + threadIdx.x) >> 5;   // 0..6143
    int lane = threadIdx.x & 31;
    int o = warp / BB;
    int b = warp & (BB - 1);
    const float* h = g_h[(TT - 1) & 1];
    const float* w = fc_w + (size_t)o * HH;
    float s = 0.f;
    #pragma unroll
    for (int i = 0; i < HH / 32; ++i) {
        int k = lane + 32 * i;
        s = fmaf(ld_cg_f1(&h[k * BB + b]), __ldg(&w[k]), s);
    }
    #pragma unroll
    for (int d = 16; d > 0; d >>= 1)
        s += __shfl_xor_sync(0xffffffffu, s, d);
    if (lane == 0) out[b * OO + o] = s + fc_b[o];
}

extern "C" void kernel_launch(void* const* d_in, const int* in_sizes, int n_in,
                              void* d_out, int out_size)
{
    const float* x    = (const float*)d_in[0];
    const float* W_ih = (const float*)d_in[1];
    const float* W_hh = (const float*)d_in[2];
    const float* b_ih = (const float*)d_in[3];
    const float* b_hh = (const float*)d_in[4];
    const float* fc_w = (const float*)d_in[5];
    const float* fc_b = (const float*)d_in[6];
    int nb = 0;
    for (int i = 0; i < n_in; ++i) {
        const float* p = (const float*)d_in[i];
        switch (in_sizes[i]) {
            case BB * TT * II: x    = p; break;
            case HH * II:      W_ih = p; break;
            case HH * HH:      W_hh = p; break;
            case OO * HH:      fc_w = p; break;
            case OO:           fc_b = p; break;
            case HH:           if (nb++ == 0) b_ih = p; else b_hh = p; break;
            default: break;
        }
    }
    float* out = (float*)d_out;

    cudaFuncSetAttribute(rnn_persistent_kernel,
                         cudaFuncAttributeMaxDynamicSharedMemorySize, SMEM_BYTES);
    rnn_persistent_kernel<<<NBLOCKS, NTHREADS, SMEM_BYTES>>>(x, W_ih, W_hh, b_ih, b_hh);
    fc_kernel<<<(BB * OO * 32) / 256, 256>>>(fc_w, fc_b, out);
}

// round 6
// speedup vs baseline: 1.5285x; 1.5250x over previous
#include <cuda_runtime.h>
#include <cstdint>

#define BB 256
#define TT 512
#define II 64
#define HH 512
#define OO 24

#define CLUSTER_NCTAS 8
#define NBLOCKS 128
#define NTHREADS 512

#define BM 16     // batch rows per cluster
#define HC 64     // hidden cols per CTA (rank)

typedef unsigned long long u64;

// Hidden state ping-pong, b-major: g_h[parity][b][h]
__device__ float g_h[2][BB * HH];

// SMEM: Hs[16][128 float4] swizzled (32KB) + Xs[16][64] (4KB)
#define HS_F4 (BM * 128)
#define XS_F  (BM * II)
#define SMEM_BYTES (HS_F4 * 16 + XS_F * 4)   // 36864

#define FFMA2(acc, a, w) \
    asm("fma.rn.f32x2 %0, %1, %2, %0;" : "+l"(acc) : "l"(a), "l"(w))

__device__ __forceinline__ float4 ld_cg_v4(const float4* p) {
    float4 v;
    asm volatile("ld.global.cg.v4.f32 {%0,%1,%2,%3}, [%4];"
                 : "=f"(v.x), "=f"(v.y), "=f"(v.z), "=f"(v.w) : "l"(p) : "memory");
    return v;
}
__device__ __forceinline__ float ld_cg_f1(const float* p) {
    float v;
    asm volatile("ld.global.cg.f32 %0, [%1];" : "=f"(v) : "l"(p) : "memory");
    return v;
}

__global__ void __launch_bounds__(NTHREADS, 1) __cluster_dims__(CLUSTER_NCTAS, 1, 1)
rnn_persistent_kernel(const float* __restrict__ x,
                      const float* __restrict__ W_ih,
                      const float* __restrict__ W_hh,
                      const float* __restrict__ b_ih,
                      const float* __restrict__ b_hh)
{
    extern __shared__ float smem[];
    float4* Hs4 = (float4*)smem;              // [b][128 f4], piece-swizzled
    float*  Xs  = smem + HS_F4 * 4;           // [b][64]
    const u64* xq = (const u64*)Xs;

    const int tid  = threadIdx.x;
    const int lane = tid & 31;
    const int warp = tid >> 5;                // 0..15
    const int rank = blockIdx.x & (CLUSTER_NCTAS - 1);
    const int cl   = blockIdx.x >> 3;
    const int b0   = cl * BM;
    const int h0   = rank * HC;
    const int hw   = h0 + 4 * warp;           // this warp's 4 h-columns
    const int k0   = lane * 16;               // this lane's k-chunk
    const int i0   = lane * 2;                // this lane's i-chunk

    // ---- register-resident weights (constant across all timesteps) ----
    u64 whh[4][8];   // [h][k-pair within chunk]
    u64 wih[4];      // [h] one i-pair
    #pragma unroll
    for (int h = 0; h < 4; ++h) {
        const ulonglong2* wrow =
            (const ulonglong2*)&W_hh[(size_t)(hw + h) * HH + k0];
        #pragma unroll
        for (int j = 0; j < 4; ++j) {
            ulonglong2 v = wrow[j];
            whh[h][2 * j]     = v.x;
            whh[h][2 * j + 1] = v.y;
        }
        wih[h] = *(const u64*)&W_ih[(size_t)(hw + h) * II + i0];
    }
    const int h_idx = 2 * (lane & 1) + ((lane >> 1) & 1);   // reduction output map
    const float biasv = b_ih[hw + h_idx] + b_hh[hw + h_idx];

    const float4* x4 = (const float4*)x;

    for (int t = 0; t < TT; ++t) {
        const float4* gprev4 = (const float4*)g_h[1 - (t & 1)];
        float*        gnew   = g_h[t & 1];

        // ---- stage h_{t-1} (b-major, coalesced) into swizzled Hs ----
        if (t > 0) {
            #pragma unroll
            for (int n = 0; n < 4; ++n) {
                int idx = tid + n * NTHREADS;
                int b = idx >> 7, p = idx & 127;
                float4 v = ld_cg_v4(gprev4 + (size_t)(b0 + b) * 128 + p);
                Hs4[b * 128 + (p ^ ((p >> 3) & 3))] = v;
            }
        }
        // ---- stage x_t ----
        if (tid < 256) {
            int b = tid >> 4, i4 = tid & 15;
            ((float4*)Xs)[b * 16 + i4] =
                x4[((size_t)(b0 + b) * TT + t) * 16 + i4];
        }
        __syncthreads();

        const bool rec = (t > 0);

        #pragma unroll 2
        for (int b = 0; b < BM; ++b) {
            u64 acc0 = 0ull, acc1 = 0ull, acc2 = 0ull, acc3 = 0ull;

            // input projection: one i-pair per lane
            u64 ax = xq[b * 32 + lane];
            FFMA2(acc0, ax, wih[0]);
            FFMA2(acc1, ax, wih[1]);
            FFMA2(acc2, ax, wih[2]);
            FFMA2(acc3, ax, wih[3]);

            // recurrent projection: 16 k per lane (4 swizzled 16B pieces)
            if (rec) {
                const ulonglong2* hrow = (const ulonglong2*)(Hs4 + b * 128);
                #pragma unroll
                for (int j = 0; j < 4; ++j) {
                    ulonglong2 v = hrow[(lane * 4 + j) ^ ((lane >> 1) & 3)];
                    FFMA2(acc0, v.x, whh[0][2 * j]);
                    FFMA2(acc0, v.y, whh[0][2 * j + 1]);
                    FFMA2(acc1, v.x, whh[1][2 * j]);
                    FFMA2(acc1, v.y, whh[1][2 * j + 1]);
                    FFMA2(acc2, v.x, whh[2][2 * j]);
                    FFMA2(acc2, v.y, whh[2][2 * j + 1]);
                    FFMA2(acc3, v.x, whh[3][2 * j]);
                    FFMA2(acc3, v.y, whh[3][2 * j + 1]);
                }
            }

            // unpack packed (even-k, odd-k) partials -> 4 scalars
            float s0, s1, s2, s3, e;
            asm("mov.b64 {%0,%1}, %2;" : "=f"(s0), "=f"(e) : "l"(acc0)); s0 += e;
            asm("mov.b64 {%0,%1}, %2;" : "=f"(s1), "=f"(e) : "l"(acc1)); s1 += e;
            asm("mov.b64 {%0,%1}, %2;" : "=f"(s2), "=f"(e) : "l"(acc2)); s2 += e;
            asm("mov.b64 {%0,%1}, %2;" : "=f"(s3), "=f"(e) : "l"(acc3)); s3 += e;

            // 6-shfl tree reduction of 4 values over 32 lanes
            bool o1 = lane & 1;
            float k0_ = o1 ? s2 : s0, k1_ = o1 ? s3 : s1;
            float g0_ = o1 ? s0 : s2, g1_ = o1 ? s1 : s3;
            k0_ += __shfl_xor_sync(0xffffffffu, g0_, 1);
            k1_ += __shfl_xor_sync(0xffffffffu, g1_, 1);
            bool o2 = lane & 2;
            float k_ = o2 ? k1_ : k0_;
            float g_ = o2 ? k0_ : k1_;
            k_ += __shfl_xor_sync(0xffffffffu, g_, 2);
            k_ += __shfl_xor_sync(0xffffffffu, k_, 4);
            k_ += __shfl_xor_sync(0xffffffffu, k_, 8);
            k_ += __shfl_xor_sync(0xffffffffu, k_, 16);

            float r = fmaxf(k_ + biasv, 0.f);
            if (lane < 4)
                gnew[(size_t)(b0 + b) * HH + hw + h_idx] = r;
        }

        // ---- cluster barrier (release h stores; also CTA-wide sync) ----
        asm volatile("fence.acq_rel.cluster;" ::: "memory");
        asm volatile("barrier.cluster.arrive.aligned;" ::: "memory");
        asm volatile("barrier.cluster.wait.aligned;"   ::: "memory");
    }
}

// Epilogue: one warp per (o,b); h is b-major -> coalesced over k.
__global__ void __launch_bounds__(256)
fc_kernel(const float* __restrict__ fc_w,
          const float* __restrict__ fc_b,
          float* __restrict__ out)
{
    int warp = (blockIdx.x * 256 + threadIdx.x) >> 5;   // 0..6143
    int lane = threadIdx.x & 31;
    int o = warp / BB;
    int b = warp & (BB - 1);
    const float* h = g_h[(TT - 1) & 1] + (size_t)b * HH;
    const float* w = fc_w + (size_t)o * HH;
    float s = 0.f;
    #pragma unroll
    for (int i = 0; i < HH / 32; ++i) {
        int k = lane + 32 * i;
        s = fmaf(ld_cg_f1(&h[k]), __ldg(&w[k]), s);
    }
    #pragma unroll
    for (int d = 16; d > 0; d >>= 1)
        s += __shfl_xor_sync(0xffffffffu, s, d);
    if (lane == 0) out[b * OO + o] = s + fc_b[o];
}

extern "C" void kernel_launch(void* const* d_in, const int* in_sizes, int n_in,
                              void* d_out, int out_size)
{
    const float* x    = (const float*)d_in[0];
    const float* W_ih = (const float*)d_in[1];
    const float* W_hh = (const float*)d_in[2];
    const float* b_ih = (const float*)d_in[3];
    const float* b_hh = (const float*)d_in[4];
    const float* fc_w = (const float*)d_in[5];
    const float* fc_b = (const float*)d_in[6];
    int nb = 0;
    for (int i = 0; i < n_in; ++i) {
        const float* p = (const float*)d_in[i];
        switch (in_sizes[i]) {
            case BB * TT * II: x    = p; break;
            case HH * II:      W_ih = p; break;
            case HH * HH:      W_hh = p; break;
            case OO * HH:      fc_w = p; break;
            case OO:           fc_b = p; break;
            case HH:           if (nb++ == 0) b_ih = p; else b_hh = p; break;
            default: break;
        }
    }
    float* out = (float*)d_out;

    cudaFuncSetAttribute(rnn_persistent_kernel,
                         cudaFuncAttributeMaxDynamicSharedMemorySize, SMEM_BYTES);
    rnn_persistent_kernel<<<NBLOCKS, NTHREADS, SMEM_BYTES>>>(x, W_ih, W_hh, b_ih, b_hh);
    fc_kernel<<<(BB * OO * 32) / 256, 256>>>(fc_w, fc_b, out);
}